// round 14
// baseline (speedup 1.0000x reference)
#include <cuda_runtime.h>
#include <stdint.h>

#define HWC    (512*512)
#define NCH    64
#define NSEG   256
#define NB     4
#define CG     16            // channels per block
#define NCG    4             // channel groups
#define CHUNK  4096          // pixels per block = 8 image rows
#define NCHP   (HWC/CHUNK)   // 64 chunks per plane
#define TPB    256
#define NWARP  8
#define STRIP  512           // px per warp = one image row
#define TPX    64            // px per warp-tile (lane owns a px pair)
#define NT     (STRIP/TPX)   // 8 tiles per warp

// Global encoded accumulator: [b][ch][s], 256KB, L2-resident.
// Zero at load; decode_kernel re-zeroes every call (graph-replay safe).
__device__ unsigned g_enc[NB * NCH * NSEG];

// Monotone float->uint encoding; enc >= 1 for any non-NaN float, 0 = identity.
__device__ __forceinline__ unsigned enc_f32(float f) {
    unsigned b = __float_as_uint(f);
    return b ^ ((unsigned)((int)b >> 31) | 0x80000000u);
}

__global__ void __launch_bounds__(TPB, 5) seg_kernel(
    const float* __restrict__ feats,   // [B, C, 512, 512]
    const int*   __restrict__ labels)  // [B, 1, 512, 512]
{
    __shared__ unsigned smax[CG * 257];     // 16.4KB; row stride 257

    const int tid  = threadIdx.x;
    const int lane = tid & 31;
    const int w    = tid >> 5;

    const int chunk = blockIdx.x;
    const int g     = blockIdx.y;
    const int b     = blockIdx.z;
    const int row   = chunk * NWARP + w;    // this warp's image row
    const int sbase = row * 512;
    const bool ybad = (row == 0) | (row == 511);

    for (int i = tid; i < CG * 257; i += TPB) smax[i] = 0u;
    __syncthreads();

    const int*   lbp = labels + (size_t)b * HWC + sbase;
    const float* fb  = feats + (size_t)(b * NCH + g * CG) * HWC + sbase;

    // Load this lane's 16 strip labels once (2 per tile), pack u8 into 4 regs.
    // Tile t labels for lane: px {t*64 + 2*lane, +1} -> coalesced int2 loads.
    unsigned labp[4];
    #pragma unroll
    for (int t2 = 0; t2 < 4; ++t2) {
        int2 a = *(const int2*)(lbp + (2 * t2)     * TPX + 2 * lane);
        int2 c = *(const int2*)(lbp + (2 * t2 + 1) * TPX + 2 * lane);
        labp[t2] = (unsigned)(a.x & 255) | ((unsigned)(a.y & 255) << 8) |
                   ((unsigned)(c.x & 255) << 16) | ((unsigned)c.y << 24);
    }

    #pragma unroll
    for (int t = 0; t < NT; ++t) {
        const unsigned lw = labp[t >> 1] >> ((t & 1) * 16);
        const unsigned l0 = lw & 255u;
        const unsigned l1 = (lw >> 8) & 255u;
        const bool bad0 = ybad | ((t == 0) & (lane == 0));
        const bool bad1 = ybad | ((t == NT - 1) & (lane == 31));
        const float* fp = fb + t * TPX + 2 * lane;

        // Two 8-channel halves: 8 outstanding LDG.64 each, then 16 ATOMS.
        #pragma unroll
        for (int hh = 0; hh < 2; ++hh) {
            float2 v[8];
            #pragma unroll
            for (int c = 0; c < 8; ++c)
                v[c] = *(const float2*)(fp + (size_t)(hh * 8 + c) * HWC);
            #pragma unroll
            for (int c = 0; c < 8; ++c) {
                unsigned e0 = bad0 ? 0u : enc_f32(v[c].x);
                unsigned e1 = bad1 ? 0u : enc_f32(v[c].y);
                atomicMax(smax + (hh * 8 + c) * 257 + l0, e0);
                atomicMax(smax + (hh * 8 + c) * 257 + l1, e1);
            }
        }
    }

    __syncthreads();
    // Dump: coalesced global RED.MAX into the L2-resident table.
    unsigned* gout = g_enc + (size_t)(b * NCH + g * CG) * NSEG;
    for (int i = tid; i < CG * NSEG; i += TPB)
        atomicMax(&gout[i], smax[(i >> 8) * 257 + (i & 255)]);
}

// Decode + reset, vectorized: 1 LDG.128 + 2 STG.128 per thread.
__global__ void __launch_bounds__(TPB) decode_kernel(float* __restrict__ out) {
    const int e4 = blockIdx.x * TPB + threadIdx.x;       // 0..16383
    uint4 m = ((const uint4*)g_enc)[e4];
    ((uint4*)g_enc)[e4] = make_uint4(0u, 0u, 0u, 0u);    // reset for next call
    float4 rv;
    rv.x = (m.x == 0u) ? 0.0f : __uint_as_float((m.x & 0x80000000u) ? (m.x ^ 0x80000000u) : ~m.x);
    rv.y = (m.y == 0u) ? 0.0f : __uint_as_float((m.y & 0x80000000u) ? (m.y ^ 0x80000000u) : ~m.y);
    rv.z = (m.z == 0u) ? 0.0f : __uint_as_float((m.z & 0x80000000u) ? (m.z ^ 0x80000000u) : ~m.z);
    rv.w = (m.w == 0u) ? 0.0f : __uint_as_float((m.w & 0x80000000u) ? (m.w ^ 0x80000000u) : ~m.w);
    ((float4*)out)[e4] = rv;
}

extern "C" void kernel_launch(void* const* d_in, const int* in_sizes, int n_in,
                              void* d_out, int out_size) {
    const float* feats  = (const float*)d_in[0];
    const int*   labels = (const int*)d_in[1];
    float*       out    = (float*)d_out;

    dim3 grid(NCHP, NCG, NB);                 // (64, 4, 4) = 1024 blocks
    seg_kernel<<<grid, TPB>>>(feats, labels);

    decode_kernel<<<(NB * NCH * NSEG) / (TPB * 4), TPB>>>(out);
}

// round 15
// speedup vs baseline: 1.2202x; 1.2202x over previous
#include <cuda_runtime.h>
#include <stdint.h>

#define HWC    (512*512)
#define NCH    64
#define NSEG   256
#define NB     4
#define CG     8             // channels per block
#define NCG    8             // channel groups
#define CHUNK  4096          // pixels per block = 8 image rows
#define NCHP   (HWC/CHUNK)   // 64 chunks per plane
#define TPB    256
#define NWARP  8
#define STRIP  512           // px per warp = one image row
#define TPX    64            // px per warp-tile (lane owns a px pair)
#define NT     (STRIP/TPX)   // 8 tiles per warp

// Global encoded accumulator: [b][ch][s], 256KB, L2-resident.
// Zero at load; decode_kernel re-zeroes every call (graph-replay safe).
__device__ unsigned g_enc[NB * NCH * NSEG];

// Monotone float->uint encoding; enc >= 1 for any non-NaN float, 0 = identity.
__device__ __forceinline__ unsigned enc_f32(float f) {
    unsigned b = __float_as_uint(f);
    return b ^ ((unsigned)((int)b >> 31) | 0x80000000u);
}

__global__ void __launch_bounds__(TPB, 5) seg_kernel(
    const float* __restrict__ feats,   // [B, C, 512, 512]
    const int*   __restrict__ labels)  // [B, 1, 512, 512]
{
    __shared__ unsigned smax[CG * 257];     // 8.2KB; row stride 257

    const int tid  = threadIdx.x;
    const int lane = tid & 31;
    const int w    = tid >> 5;

    const int chunk = blockIdx.x;
    const int g     = blockIdx.y;
    const int b     = blockIdx.z;
    const int row   = chunk * NWARP + w;    // this warp's image row
    const int sbase = row * 512;
    const bool ybad = (row == 0) | (row == 511);

    for (int i = tid; i < CG * 257; i += TPB) smax[i] = 0u;
    __syncthreads();

    const int*   lbp = labels + (size_t)b * HWC + sbase;
    const float* fb  = feats + (size_t)(b * NCH + g * CG) * HWC + sbase;

    // Load this lane's 16 strip labels once (2 per tile), pack u8 into 4 regs.
    // int32 labels straight from gmem (L2-resident: 4MB total, re-read by 8 g's).
    unsigned labp[4];
    #pragma unroll
    for (int t2 = 0; t2 < 4; ++t2) {
        int2 a = *(const int2*)(lbp + (2 * t2)     * TPX + 2 * lane);
        int2 c = *(const int2*)(lbp + (2 * t2 + 1) * TPX + 2 * lane);
        labp[t2] = (unsigned)(a.x & 255) | ((unsigned)(a.y & 255) << 8) |
                   ((unsigned)(c.x & 255) << 16) | ((unsigned)c.y << 24);
    }

    // Prefetch tile 0 values: lane owns px pair {2*lane, 2*lane+1}.
    float2 cur[CG];
    {
        const float* fp = fb + 2 * lane;
        #pragma unroll
        for (int c = 0; c < CG; ++c)
            cur[c] = *(const float2*)(fp + (size_t)c * HWC);
    }

    #pragma unroll
    for (int t = 0; t < NT; ++t) {
        // Prefetch next tile into fresh registers (unrolled -> rotation free).
        float2 nxt[CG];
        if (t + 1 < NT) {
            const float* fp = fb + (t + 1) * TPX + 2 * lane;
            #pragma unroll
            for (int c = 0; c < CG; ++c)
                nxt[c] = *(const float2*)(fp + (size_t)c * HWC);
        }

        // Atomics straight from registers; border px -> enc 0 (max identity).
        {
            const unsigned lw = labp[t >> 1] >> ((t & 1) * 16);
            const unsigned l0 = lw & 255u;
            const unsigned l1 = (lw >> 8) & 255u;
            const bool bad0 = ybad | ((t == 0) & (lane == 0));
            const bool bad1 = ybad | ((t == NT - 1) & (lane == 31));
            #pragma unroll
            for (int c = 0; c < CG; ++c) {
                unsigned e0 = bad0 ? 0u : enc_f32(cur[c].x);
                unsigned e1 = bad1 ? 0u : enc_f32(cur[c].y);
                atomicMax(smax + c * 257 + l0, e0);
                atomicMax(smax + c * 257 + l1, e1);
            }
        }

        #pragma unroll
        for (int c = 0; c < CG; ++c) cur[c] = nxt[c];
    }

    __syncthreads();
    // Dump: coalesced global RED.MAX into the L2-resident table.
    unsigned* gout = g_enc + (size_t)(b * NCH + g * CG) * NSEG;
    for (int i = tid; i < CG * NSEG; i += TPB)
        atomicMax(&gout[i], smax[(i >> 8) * 257 + (i & 255)]);
}

// Decode + reset, vectorized: 1 LDG.128 + 2 STG.128 per thread.
__global__ void __launch_bounds__(TPB) decode_kernel(float* __restrict__ out) {
    const int e4 = blockIdx.x * TPB + threadIdx.x;       // 0..16383
    uint4 m = ((const uint4*)g_enc)[e4];
    ((uint4*)g_enc)[e4] = make_uint4(0u, 0u, 0u, 0u);    // reset for next call
    float4 rv;
    rv.x = (m.x == 0u) ? 0.0f : __uint_as_float((m.x & 0x80000000u) ? (m.x ^ 0x80000000u) : ~m.x);
    rv.y = (m.y == 0u) ? 0.0f : __uint_as_float((m.y & 0x80000000u) ? (m.y ^ 0x80000000u) : ~m.y);
    rv.z = (m.z == 0u) ? 0.0f : __uint_as_float((m.z & 0x80000000u) ? (m.z ^ 0x80000000u) : ~m.z);
    rv.w = (m.w == 0u) ? 0.0f : __uint_as_float((m.w & 0x80000000u) ? (m.w ^ 0x80000000u) : ~m.w);
    ((float4*)out)[e4] = rv;
}

extern "C" void kernel_launch(void* const* d_in, const int* in_sizes, int n_in,
                              void* d_out, int out_size) {
    const float* feats  = (const float*)d_in[0];
    const int*   labels = (const int*)d_in[1];
    float*       out    = (float*)d_out;

    dim3 grid(NCHP, NCG, NB);                 // (64, 8, 4) = 2048 blocks
    seg_kernel<<<grid, TPB>>>(feats, labels);

    decode_kernel<<<(NB * NCH * NSEG) / (TPB * 4), TPB>>>(out);
}